// round 1
// baseline (speedup 1.0000x reference)
#include <cuda_runtime.h>
#include <math.h>

// Problem constants (compile-time from the reference)
#define Bn      2048
#define LATENT  128
#define NCLS    8
#define HID     1024
#define Dd      512
#define NMAXP   4096

__device__ __constant__ int d_COUNTS[NCLS] = {1024, 1536, 2048, 2560, 3072, 3584, 3840, 4096};

// Scratch (static device memory; no allocation allowed)
__device__ float g_h[Bn * HID];                 // 8 MB
__device__ float g_t[Bn * HID];                 // 8 MB
__device__ float g_logits[(size_t)Bn * NMAXP];  // 32 MB (reused in-place as alpha)
__device__ int   g_cnt[NCLS];
__device__ int   g_off[NCLS];
__device__ int   g_fill[NCLS];
__device__ int   g_rowidx[Bn];

__device__ __forceinline__ float gelu_exact(float x) {
    return 0.5f * x * (1.0f + erff(x * 0.70710678118654752440f));
}

// ---------------- class bucketing ----------------
__global__ void k_zero() {
    int t = threadIdx.x;
    if (t < NCLS) { g_cnt[t] = 0; g_fill[t] = 0; }
}

__global__ void k_count(const int* __restrict__ cid) {
    int b = blockIdx.x * 256 + threadIdx.x;
    if (b < Bn) atomicAdd(&g_cnt[cid[b]], 1);
}

__global__ void k_prefix() {
    int acc = 0;
    for (int c = 0; c < NCLS; c++) { g_off[c] = acc; acc += g_cnt[c]; }
}

__global__ void k_scatter(const int* __restrict__ cid) {
    int b = blockIdx.x * 256 + threadIdx.x;
    if (b < Bn) {
        int c = cid[b];
        int pos = g_off[c] + atomicAdd(&g_fill[c], 1);
        g_rowidx[pos] = b;
    }
}

// ---------------- GEMM1: h = gelu(z @ W1[:128] + W1[128+cid] + b1) ----------------
// C tile 128x128, K=128, 256 threads, 8x8 micro-tile.
__global__ void __launch_bounds__(256) k_gemm1(
    const float* __restrict__ z, const int* __restrict__ cid,
    const float* __restrict__ W1, const float* __restrict__ b1)
{
    const int n0 = blockIdx.x * 128;
    const int m0 = blockIdx.y * 128;
    __shared__ float As[8][128];
    __shared__ float Bs[8][128];
    float acc[8][8] = {};

    const int tid  = threadIdx.x;
    const int arow = tid >> 1, ak4 = (tid & 1) * 4;
    const int bk   = tid >> 5, bn4 = (tid & 31) * 4;
    const int ty   = tid >> 4, tx  = tid & 15;

    const float* aptr = z + (size_t)(m0 + arow) * LATENT + ak4;
    const float* bptr = W1 + (size_t)bk * HID + n0 + bn4;

    for (int k0 = 0; k0 < LATENT; k0 += 8) {
        float4 av = *(const float4*)(aptr + k0);
        As[ak4 + 0][arow] = av.x; As[ak4 + 1][arow] = av.y;
        As[ak4 + 2][arow] = av.z; As[ak4 + 3][arow] = av.w;
        *(float4*)&Bs[bk][bn4] = *(const float4*)(bptr + (size_t)k0 * HID);
        __syncthreads();
#pragma unroll
        for (int kk = 0; kk < 8; kk++) {
            float a[8], b[8];
            *(float4*)(a)     = *(const float4*)&As[kk][ty * 8];
            *(float4*)(a + 4) = *(const float4*)&As[kk][ty * 8 + 4];
            *(float4*)(b)     = *(const float4*)&Bs[kk][tx * 8];
            *(float4*)(b + 4) = *(const float4*)&Bs[kk][tx * 8 + 4];
#pragma unroll
            for (int i = 0; i < 8; i++)
#pragma unroll
                for (int j = 0; j < 8; j++) acc[i][j] += a[i] * b[j];
        }
        __syncthreads();
    }

#pragma unroll
    for (int i = 0; i < 8; i++) {
        int row = m0 + ty * 8 + i;
        int c   = cid[row];
        const float* wext = W1 + (size_t)(LATENT + c) * HID;
#pragma unroll
        for (int j = 0; j < 8; j++) {
            int col = n0 + tx * 8 + j;
            float v = acc[i][j] + b1[col] + wext[col];
            g_h[(size_t)row * HID + col] = gelu_exact(v);
        }
    }
}

// ---------------- GEMM2: t = gelu(h @ W2 + b2) ----------------
__global__ void __launch_bounds__(256) k_gemm2(
    const float* __restrict__ W2, const float* __restrict__ b2)
{
    const int n0 = blockIdx.x * 128;
    const int m0 = blockIdx.y * 128;
    __shared__ float As[8][128];
    __shared__ float Bs[8][128];
    float acc[8][8] = {};

    const int tid  = threadIdx.x;
    const int arow = tid >> 1, ak4 = (tid & 1) * 4;
    const int bk   = tid >> 5, bn4 = (tid & 31) * 4;
    const int ty   = tid >> 4, tx  = tid & 15;

    const float* aptr = g_h + (size_t)(m0 + arow) * HID + ak4;
    const float* bptr = W2 + (size_t)bk * HID + n0 + bn4;

    for (int k0 = 0; k0 < HID; k0 += 8) {
        float4 av = *(const float4*)(aptr + k0);
        As[ak4 + 0][arow] = av.x; As[ak4 + 1][arow] = av.y;
        As[ak4 + 2][arow] = av.z; As[ak4 + 3][arow] = av.w;
        *(float4*)&Bs[bk][bn4] = *(const float4*)(bptr + (size_t)k0 * HID);
        __syncthreads();
#pragma unroll
        for (int kk = 0; kk < 8; kk++) {
            float a[8], b[8];
            *(float4*)(a)     = *(const float4*)&As[kk][ty * 8];
            *(float4*)(a + 4) = *(const float4*)&As[kk][ty * 8 + 4];
            *(float4*)(b)     = *(const float4*)&Bs[kk][tx * 8];
            *(float4*)(b + 4) = *(const float4*)&Bs[kk][tx * 8 + 4];
#pragma unroll
            for (int i = 0; i < 8; i++)
#pragma unroll
                for (int j = 0; j < 8; j++) acc[i][j] += a[i] * b[j];
        }
        __syncthreads();
    }

#pragma unroll
    for (int i = 0; i < 8; i++) {
        int row = m0 + ty * 8 + i;
#pragma unroll
        for (int j = 0; j < 8; j++) {
            int col = n0 + tx * 8 + j;
            g_t[(size_t)row * HID + col] = gelu_exact(acc[i][j] + b2[col]);
        }
    }
}

// ---------------- logits = t_gathered @ Wa[c] + ba[c]  (grouped by class) ----------------
__global__ void __launch_bounds__(256) k_logits(
    const float* __restrict__ Wa, const float* __restrict__ ba)
{
    const int c = blockIdx.z;
    const int mcnt = g_cnt[c];
    const int m0 = blockIdx.y * 128;
    if (m0 >= mcnt) return;
    const int n0 = blockIdx.x * 128;
    if (n0 >= d_COUNTS[c]) return;

    __shared__ int   rows[128];
    __shared__ float As[8][128];
    __shared__ float Bs[8][128];
    float acc[8][8] = {};

    const int tid = threadIdx.x;
    if (tid < 128) {
        int mi = m0 + tid;
        rows[tid] = g_rowidx[g_off[c] + (mi < mcnt ? mi : 0)];
    }
    __syncthreads();

    const int arow = tid >> 1, ak4 = (tid & 1) * 4;
    const int bk   = tid >> 5, bn4 = (tid & 31) * 4;
    const int ty   = tid >> 4, tx  = tid & 15;

    const float* aptr = g_t + (size_t)rows[arow] * HID + ak4;
    const float* bptr = Wa + (size_t)c * HID * NMAXP + (size_t)bk * NMAXP + n0 + bn4;

    for (int k0 = 0; k0 < HID; k0 += 8) {
        float4 av = *(const float4*)(aptr + k0);
        As[ak4 + 0][arow] = av.x; As[ak4 + 1][arow] = av.y;
        As[ak4 + 2][arow] = av.z; As[ak4 + 3][arow] = av.w;
        *(float4*)&Bs[bk][bn4] = *(const float4*)(bptr + (size_t)k0 * NMAXP);
        __syncthreads();
#pragma unroll
        for (int kk = 0; kk < 8; kk++) {
            float a[8], b[8];
            *(float4*)(a)     = *(const float4*)&As[kk][ty * 8];
            *(float4*)(a + 4) = *(const float4*)&As[kk][ty * 8 + 4];
            *(float4*)(b)     = *(const float4*)&Bs[kk][tx * 8];
            *(float4*)(b + 4) = *(const float4*)&Bs[kk][tx * 8 + 4];
#pragma unroll
            for (int i = 0; i < 8; i++)
#pragma unroll
                for (int j = 0; j < 8; j++) acc[i][j] += a[i] * b[j];
        }
        __syncthreads();
    }

    const float* bap = ba + (size_t)c * NMAXP;
#pragma unroll
    for (int i = 0; i < 8; i++) {
        int mi = m0 + ty * 8 + i;
        if (mi < mcnt) {
            int row = rows[ty * 8 + i];
#pragma unroll
            for (int j = 0; j < 8; j++) {
                int col = n0 + tx * 8 + j;
                g_logits[(size_t)row * NMAXP + col] = acc[i][j] + bap[col];
            }
        }
    }
}

// ---------------- softmax over the valid prefix (in-place) ----------------
__global__ void __launch_bounds__(256) k_softmax(const int* __restrict__ cid) {
    const int b = blockIdx.x;
    const int c = cid[b];
    const int n = d_COUNTS[c];
    float* Lrow = g_logits + (size_t)b * NMAXP;
    const int tid = threadIdx.x;

    float v[16];
    int cnt = 0;
    float mx = -INFINITY;
    for (int i = tid; i < n; i += 256) {
        float x = Lrow[i];
        v[cnt++] = x;
        mx = fmaxf(mx, x);
    }

    __shared__ float red[8];
#pragma unroll
    for (int o = 16; o; o >>= 1) mx = fmaxf(mx, __shfl_xor_sync(0xFFFFFFFFu, mx, o));
    if ((tid & 31) == 0) red[tid >> 5] = mx;
    __syncthreads();
    mx = red[0];
#pragma unroll
    for (int w = 1; w < 8; w++) mx = fmaxf(mx, red[w]);
    __syncthreads();

    float s = 0.0f;
    for (int k = 0; k < cnt; k++) {
        float e = expf(v[k] - mx);
        v[k] = e;
        s += e;
    }
#pragma unroll
    for (int o = 16; o; o >>= 1) s += __shfl_xor_sync(0xFFFFFFFFu, s, o);
    if ((tid & 31) == 0) red[tid >> 5] = s;
    __syncthreads();
    s = red[0];
#pragma unroll
    for (int w = 1; w < 8; w++) s += red[w];
    const float inv = 1.0f / s;

    int k = 0;
    for (int i = tid; i < n; i += 256) Lrow[i] = v[k++] * inv;
}

// ---------------- synth: out = alpha_gathered @ Xbuf[c]  (grouped by class) ----------------
__global__ void __launch_bounds__(256) k_synth(
    const float* __restrict__ Xbuf, float* __restrict__ out)
{
    const int c = blockIdx.z;
    const int mcnt = g_cnt[c];
    const int m0 = blockIdx.y * 128;
    if (m0 >= mcnt) return;
    const int n0 = blockIdx.x * 128;
    const int K  = d_COUNTS[c];

    __shared__ int   rows[128];
    __shared__ float As[8][128];
    __shared__ float Bs[8][128];
    float acc[8][8] = {};

    const int tid = threadIdx.x;
    if (tid < 128) {
        int mi = m0 + tid;
        rows[tid] = g_rowidx[g_off[c] + (mi < mcnt ? mi : 0)];
    }
    __syncthreads();

    const int arow = tid >> 1, ak4 = (tid & 1) * 4;
    const int bk   = tid >> 5, bn4 = (tid & 31) * 4;
    const int ty   = tid >> 4, tx  = tid & 15;

    const float* aptr = g_logits + (size_t)rows[arow] * NMAXP + ak4;
    const float* bptr = Xbuf + (size_t)c * NMAXP * Dd + (size_t)bk * Dd + n0 + bn4;

    for (int k0 = 0; k0 < K; k0 += 8) {
        float4 av = *(const float4*)(aptr + k0);
        As[ak4 + 0][arow] = av.x; As[ak4 + 1][arow] = av.y;
        As[ak4 + 2][arow] = av.z; As[ak4 + 3][arow] = av.w;
        *(float4*)&Bs[bk][bn4] = *(const float4*)(bptr + (size_t)k0 * Dd);
        __syncthreads();
#pragma unroll
        for (int kk = 0; kk < 8; kk++) {
            float a[8], b[8];
            *(float4*)(a)     = *(const float4*)&As[kk][ty * 8];
            *(float4*)(a + 4) = *(const float4*)&As[kk][ty * 8 + 4];
            *(float4*)(b)     = *(const float4*)&Bs[kk][tx * 8];
            *(float4*)(b + 4) = *(const float4*)&Bs[kk][tx * 8 + 4];
#pragma unroll
            for (int i = 0; i < 8; i++)
#pragma unroll
                for (int j = 0; j < 8; j++) acc[i][j] += a[i] * b[j];
        }
        __syncthreads();
    }

#pragma unroll
    for (int i = 0; i < 8; i++) {
        int mi = m0 + ty * 8 + i;
        if (mi < mcnt) {
            int row = rows[ty * 8 + i];
#pragma unroll
            for (int j = 0; j < 8; j++) {
                int col = n0 + tx * 8 + j;
                out[(size_t)row * Dd + col] = acc[i][j];
            }
        }
    }
}

// ---------------- launch ----------------
extern "C" void kernel_launch(void* const* d_in, const int* in_sizes, int n_in,
                              void* d_out, int out_size) {
    const float* z    = (const float*)d_in[0];
    const int*   cid  = (const int*)  d_in[1];
    const float* W1   = (const float*)d_in[2];
    const float* b1   = (const float*)d_in[3];
    const float* W2   = (const float*)d_in[4];
    const float* b2   = (const float*)d_in[5];
    const float* Wa   = (const float*)d_in[6];
    const float* ba   = (const float*)d_in[7];
    const float* Xbuf = (const float*)d_in[8];
    float* out = (float*)d_out;

    k_zero<<<1, 32>>>();
    k_count<<<Bn / 256, 256>>>(cid);
    k_prefix<<<1, 1>>>();
    k_scatter<<<Bn / 256, 256>>>(cid);

    k_gemm1<<<dim3(HID / 128, Bn / 128), 256>>>(z, cid, W1, b1);
    k_gemm2<<<dim3(HID / 128, Bn / 128), 256>>>(W2, b2);
    k_logits<<<dim3(NMAXP / 128, Bn / 128, NCLS), 256>>>(Wa, ba);
    k_softmax<<<Bn, 256>>>(cid);
    k_synth<<<dim3(Dd / 128, Bn / 128, NCLS), 256>>>(Xbuf, out);
}

// round 3
// speedup vs baseline: 4.2786x; 4.2786x over previous
#include <cuda_runtime.h>
#include <cuda_bf16.h>
#include <math.h>
#include <stdint.h>

// Problem constants
#define Bn      2048
#define LATENT  128
#define NCLS    8
#define HID     1024
#define Dd      512
#define NMAXP   4096

#define PK          40                      // padded k-stride (bf16 elements), 80B rows
#define PLANE       (128 * PK * 2)          // 10240 B, one bf16 plane
#define STAGE       (4 * PLANE)             // AHI, ALO, BHI, BLO = 40960 B
#define SMEM_BYTES  (2 * STAGE)             // 81920 B double buffered

__device__ __constant__ int d_COUNTS[NCLS] = {1024, 1536, 2048, 2560, 3072, 3584, 3840, 4096};

__device__ float g_h[Bn * HID];
__device__ float g_t[Bn * HID];
__device__ float g_logits[(size_t)Bn * NMAXP];
__device__ int   g_cnt[NCLS];
__device__ int   g_off[NCLS];
__device__ int   g_fill[NCLS];
__device__ int   g_rowidx[Bn];

// ---------------- helpers ----------------
__device__ __forceinline__ uint32_t smem_u32(const void* p) {
    uint32_t a;
    asm("{ .reg .u64 t; cvta.to.shared.u64 t, %1; cvt.u32.u64 %0, t; }" : "=r"(a) : "l"(p));
    return a;
}
__device__ __forceinline__ uint32_t pk2(__nv_bfloat16 a, __nv_bfloat16 b) {
    return (uint32_t)__bfloat16_as_ushort(a) | ((uint32_t)__bfloat16_as_ushort(b) << 16);
}
__device__ __forceinline__ void split2(float x, __nv_bfloat16& h, __nv_bfloat16& l) {
    h = __float2bfloat16(x);
    l = __float2bfloat16(x - __bfloat162float(h));
}
__device__ __forceinline__ float gelu_exact(float x) {
    return 0.5f * x * (1.0f + erff(x * 0.70710678118654752440f));
}

__device__ __forceinline__ void ldm_x4(uint32_t addr, uint32_t* r) {
    asm volatile("ldmatrix.sync.aligned.m8n8.x4.shared.b16 {%0,%1,%2,%3}, [%4];"
        : "=r"(r[0]), "=r"(r[1]), "=r"(r[2]), "=r"(r[3]) : "r"(addr));
}
__device__ __forceinline__ void ldm_x2(uint32_t addr, uint32_t* r) {
    asm volatile("ldmatrix.sync.aligned.m8n8.x2.shared.b16 {%0,%1}, [%2];"
        : "=r"(r[0]), "=r"(r[1]) : "r"(addr));
}
__device__ __forceinline__ void mma16816(float* c, const uint32_t* a, const uint32_t* b) {
    asm volatile(
        "mma.sync.aligned.m16n8k16.row.col.f32.bf16.bf16.f32 "
        "{%0,%1,%2,%3}, {%4,%5,%6,%7}, {%8,%9}, {%0,%1,%2,%3};"
        : "+f"(c[0]), "+f"(c[1]), "+f"(c[2]), "+f"(c[3])
        : "r"(a[0]), "r"(a[1]), "r"(a[2]), "r"(a[3]), "r"(b[0]), "r"(b[1]));
}

// ---------------- mainloop building blocks ----------------
// Fetch one K=32 chunk into registers (global loads only).
template<bool GATHER>
__device__ __forceinline__ void fetch_chunk(
    const float* __restrict__ A, int lda,
    const float* __restrict__ Bg, int ldb,
    int k0, int m0, int n0, const int* rowsm, int tid,
    float4 af[4], float2 bfv[8])
{
#pragma unroll
    for (int it = 0; it < 4; ++it) {
        int idx = tid + it * 256;
        int r = idx >> 3, q = idx & 7;
        int src = GATHER ? rowsm[r] : (m0 + r);
        af[it] = *(const float4*)(A + (size_t)src * lda + k0 + q * 4);
    }
#pragma unroll
    for (int it = 0; it < 8; ++it) {
        int e = tid + it * 256;
        int kp = e >> 7, n = e & 127;
        const float* bp = Bg + (size_t)(k0 + 2 * kp) * ldb + n0 + n;
        bfv[it].x = bp[0];
        bfv[it].y = bp[ldb];
    }
}

// Convert + store fetched chunk to a stage buffer.
__device__ __forceinline__ void store_stage(char* buf, int tid,
                                            const float4 af[4], const float2 bfv[8])
{
    char* AHI = buf;
    char* ALO = buf + PLANE;
    char* BHI = buf + 2 * PLANE;
    char* BLO = buf + 3 * PLANE;
#pragma unroll
    for (int it = 0; it < 4; ++it) {
        int idx = tid + it * 256;
        int r = idx >> 3, q = idx & 7;
        __nv_bfloat16 h0, h1, h2, h3, l0, l1, l2, l3;
        split2(af[it].x, h0, l0); split2(af[it].y, h1, l1);
        split2(af[it].z, h2, l2); split2(af[it].w, h3, l3);
        uint32_t off = (uint32_t)(r * PK + q * 4) * 2;
        *(uint2*)(AHI + off) = make_uint2(pk2(h0, h1), pk2(h2, h3));
        *(uint2*)(ALO + off) = make_uint2(pk2(l0, l1), pk2(l2, l3));
    }
#pragma unroll
    for (int it = 0; it < 8; ++it) {
        int e = tid + it * 256;
        int kp = e >> 7, n = e & 127;
        __nv_bfloat16 hx, hy, lx, ly;
        split2(bfv[it].x, hx, lx);
        split2(bfv[it].y, hy, ly);
        uint32_t off = (uint32_t)(n * PK + 2 * kp) * 2;
        *(uint32_t*)(BHI + off) = pk2(hx, hy);
        *(uint32_t*)(BLO + off) = pk2(lx, ly);
    }
}

// Compute one K=32 chunk from a stage buffer (2 k16 steps, 3-product bf16 split).
__device__ __forceinline__ void compute_stage(uint32_t sbase, int lane, int wm, int wn,
                                              float acc[4][4][4])
{
#pragma unroll
    for (int ks = 0; ks < 2; ++ks) {
        uint32_t ahi[4][4], alo[4][4];
#pragma unroll
        for (int mt = 0; mt < 4; ++mt) {
            uint32_t row = (uint32_t)(wm + mt * 16 + (lane & 15));
            uint32_t addr = sbase + (row * PK + ks * 16) * 2 + ((uint32_t)(lane >> 4)) * 16;
            ldm_x4(addr, ahi[mt]);
            ldm_x4(addr + PLANE, alo[mt]);
        }
#pragma unroll
        for (int nt = 0; nt < 4; ++nt) {
            uint32_t nrow = (uint32_t)(wn + nt * 8 + (lane & 7));
            uint32_t baddr = sbase + 2 * PLANE + (nrow * PK + ks * 16) * 2
                           + ((uint32_t)((lane >> 3) & 1)) * 16;
            uint32_t bhi[2], blo[2];
            ldm_x2(baddr, bhi);
            ldm_x2(baddr + PLANE, blo);
#pragma unroll
            for (int mt = 0; mt < 4; ++mt) {
                mma16816(acc[mt][nt], ahi[mt], bhi);
                mma16816(acc[mt][nt], ahi[mt], blo);
                mma16816(acc[mt][nt], alo[mt], bhi);
            }
        }
    }
}

// Full mainloop: double-buffered, fetch(s+1) overlapped with compute(s).
template<bool GATHER>
__device__ __forceinline__ void mma_mainloop(
    const float* __restrict__ A, int lda,
    const float* __restrict__ Bg, int ldb, int K,
    char* sm, uint32_t smb, const int* rowsm, int m0, int n0,
    float acc[4][4][4])
{
    const int tid = threadIdx.x;
    const int lane = tid & 31, warp = tid >> 5;
    const int wm = (warp & 1) * 64, wn = (warp >> 1) * 32;
    const int S = K >> 5;

    float4 af[4]; float2 bfv[8];
    fetch_chunk<GATHER>(A, lda, Bg, ldb, 0, m0, n0, rowsm, tid, af, bfv);
    store_stage(sm, tid, af, bfv);
    __syncthreads();

    for (int s = 0; s < S; ++s) {
        const int b = s & 1;
        if (s + 1 < S)
            fetch_chunk<GATHER>(A, lda, Bg, ldb, (s + 1) << 5, m0, n0, rowsm, tid, af, bfv);
        compute_stage(smb + b * STAGE, lane, wm, wn, acc);
        __syncthreads();
        if (s + 1 < S) {
            store_stage(sm + (b ^ 1) * STAGE, tid, af, bfv);
        }
        __syncthreads();
    }
}

// ---------------- bucketing ----------------
__global__ void k_zero() {
    int t = threadIdx.x;
    if (t < NCLS) { g_cnt[t] = 0; g_fill[t] = 0; }
}
__global__ void k_count(const int* __restrict__ cid) {
    int b = blockIdx.x * 256 + threadIdx.x;
    if (b < Bn) atomicAdd(&g_cnt[cid[b]], 1);
}
__global__ void k_prefix() {
    int acc = 0;
    for (int c = 0; c < NCLS; c++) { g_off[c] = acc; acc += g_cnt[c]; }
}
__global__ void k_scatter(const int* __restrict__ cid) {
    int b = blockIdx.x * 256 + threadIdx.x;
    if (b < Bn) {
        int c = cid[b];
        g_rowidx[g_off[c] + atomicAdd(&g_fill[c], 1)] = b;
    }
}

// ---------------- GEMM kernels ----------------
__global__ void __launch_bounds__(256, 1)
k_mma_gemm1(const float* __restrict__ z, const int* __restrict__ cid,
            const float* __restrict__ W1, const float* __restrict__ b1)
{
    extern __shared__ char sm[];
    const int n0 = blockIdx.x * 128, m0 = blockIdx.y * 128;
    const uint32_t smb = smem_u32(sm);
    const int tid = threadIdx.x, lane = tid & 31, warp = tid >> 5;
    const int wm = (warp & 1) * 64, wn = (warp >> 1) * 32;

    float acc[4][4][4] = {};
    mma_mainloop<false>(z, LATENT, W1, HID, LATENT, sm, smb, nullptr, m0, n0, acc);

#pragma unroll
    for (int mt = 0; mt < 4; ++mt) {
        int r0 = wm + mt * 16 + (lane >> 2);
#pragma unroll
        for (int half = 0; half < 2; ++half) {
            int row = m0 + r0 + half * 8;
            int c = cid[row];
            const float* wext = W1 + (size_t)(LATENT + c) * HID;
#pragma unroll
            for (int nt = 0; nt < 4; ++nt) {
                int col = n0 + wn + nt * 8 + (lane & 3) * 2;
                float v0 = acc[mt][nt][half * 2 + 0] + b1[col]     + wext[col];
                float v1 = acc[mt][nt][half * 2 + 1] + b1[col + 1] + wext[col + 1];
                *(float2*)(g_h + (size_t)row * HID + col) =
                    make_float2(gelu_exact(v0), gelu_exact(v1));
            }
        }
    }
}

__global__ void __launch_bounds__(256, 1)
k_mma_gemm2(const float* __restrict__ W2, const float* __restrict__ b2)
{
    extern __shared__ char sm[];
    const int n0 = blockIdx.x * 128, m0 = blockIdx.y * 128;
    const uint32_t smb = smem_u32(sm);
    const int tid = threadIdx.x, lane = tid & 31, warp = tid >> 5;
    const int wm = (warp & 1) * 64, wn = (warp >> 1) * 32;

    float acc[4][4][4] = {};
    mma_mainloop<false>(g_h, HID, W2, HID, HID, sm, smb, nullptr, m0, n0, acc);

#pragma unroll
    for (int mt = 0; mt < 4; ++mt) {
        int r0 = wm + mt * 16 + (lane >> 2);
#pragma unroll
        for (int half = 0; half < 2; ++half) {
            int row = m0 + r0 + half * 8;
#pragma unroll
            for (int nt = 0; nt < 4; ++nt) {
                int col = n0 + wn + nt * 8 + (lane & 3) * 2;
                float v0 = acc[mt][nt][half * 2 + 0] + b2[col];
                float v1 = acc[mt][nt][half * 2 + 1] + b2[col + 1];
                *(float2*)(g_t + (size_t)row * HID + col) =
                    make_float2(gelu_exact(v0), gelu_exact(v1));
            }
        }
    }
}

__global__ void __launch_bounds__(256, 1)
k_mma_logits(const float* __restrict__ Wa, const float* __restrict__ ba)
{
    extern __shared__ char sm[];
    __shared__ int rows[128];
    const int c = blockIdx.z;
    const int mcnt = g_cnt[c];
    const int m0 = blockIdx.y * 128;
    if (m0 >= mcnt) return;
    const int n0 = blockIdx.x * 128;
    if (n0 >= d_COUNTS[c]) return;

    const uint32_t smb = smem_u32(sm);
    const int tid = threadIdx.x, lane = tid & 31, warp = tid >> 5;
    const int wm = (warp & 1) * 64, wn = (warp >> 1) * 32;

    if (tid < 128) {
        int mi = m0 + tid;
        rows[tid] = g_rowidx[g_off[c] + (mi < mcnt ? mi : 0)];
    }
    __syncthreads();

    float acc[4][4][4] = {};
    mma_mainloop<true>(g_t, HID, Wa + (size_t)c * HID * NMAXP, NMAXP, HID,
                       sm, smb, rows, m0, n0, acc);

    const float* bap = ba + (size_t)c * NMAXP;
#pragma unroll
    for (int mt = 0; mt < 4; ++mt) {
        int r0 = wm + mt * 16 + (lane >> 2);
#pragma unroll
        for (int half = 0; half < 2; ++half) {
            int mi = r0 + half * 8;
            if (m0 + mi < mcnt) {
                int grow = rows[mi];
#pragma unroll
                for (int nt = 0; nt < 4; ++nt) {
                    int col = n0 + wn + nt * 8 + (lane & 3) * 2;
                    float v0 = acc[mt][nt][half * 2 + 0] + bap[col];
                    float v1 = acc[mt][nt][half * 2 + 1] + bap[col + 1];
                    *(float2*)(g_logits + (size_t)grow * NMAXP + col) = make_float2(v0, v1);
                }
            }
        }
    }
}

__global__ void __launch_bounds__(256, 1)
k_mma_synth(const float* __restrict__ Xbuf, float* __restrict__ out)
{
    extern __shared__ char sm[];
    __shared__ int rows[128];
    const int c = blockIdx.z;
    const int mcnt = g_cnt[c];
    const int m0 = blockIdx.y * 128;
    if (m0 >= mcnt) return;
    const int n0 = blockIdx.x * 128;
    const int K = d_COUNTS[c];

    const uint32_t smb = smem_u32(sm);
    const int tid = threadIdx.x, lane = tid & 31, warp = tid >> 5;
    const int wm = (warp & 1) * 64, wn = (warp >> 1) * 32;

    if (tid < 128) {
        int mi = m0 + tid;
        rows[tid] = g_rowidx[g_off[c] + (mi < mcnt ? mi : 0)];
    }
    __syncthreads();

    float acc[4][4][4] = {};
    mma_mainloop<true>(g_logits, NMAXP, Xbuf + (size_t)c * NMAXP * Dd, Dd, K,
                       sm, smb, rows, m0, n0, acc);

#pragma unroll
    for (int mt = 0; mt < 4; ++mt) {
        int r0 = wm + mt * 16 + (lane >> 2);
#pragma unroll
        for (int half = 0; half < 2; ++half) {
            int mi = r0 + half * 8;
            if (m0 + mi < mcnt) {
                int grow = rows[mi];
#pragma unroll
                for (int nt = 0; nt < 4; ++nt) {
                    int col = n0 + wn + nt * 8 + (lane & 3) * 2;
                    *(float2*)(out + (size_t)grow * Dd + col) =
                        make_float2(acc[mt][nt][half * 2 + 0], acc[mt][nt][half * 2 + 1]);
                }
            }
        }
    }
}

// ---------------- softmax over valid prefix (in-place on g_logits) ----------------
__global__ void __launch_bounds__(256) k_softmax(const int* __restrict__ cid) {
    const int b = blockIdx.x;
    const int c = cid[b];
    const int n = d_COUNTS[c];
    float* Lrow = g_logits + (size_t)b * NMAXP;
    const int tid = threadIdx.x;

    float v[16];
    int cnt = 0;
    float mx = -INFINITY;
    for (int i = tid; i < n; i += 256) {
        float x = Lrow[i];
        v[cnt++] = x;
        mx = fmaxf(mx, x);
    }
    __shared__ float red[8];
#pragma unroll
    for (int o = 16; o; o >>= 1) mx = fmaxf(mx, __shfl_xor_sync(0xFFFFFFFFu, mx, o));
    if ((tid & 31) == 0) red[tid >> 5] = mx;
    __syncthreads();
    mx = red[0];
#pragma unroll
    for (int w = 1; w < 8; w++) mx = fmaxf(mx, red[w]);
    __syncthreads();

    float s = 0.0f;
    for (int k = 0; k < cnt; k++) {
        float e = expf(v[k] - mx);
        v[k] = e;
        s += e;
    }
#pragma unroll
    for (int o = 16; o; o >>= 1) s += __shfl_xor_sync(0xFFFFFFFFu, s, o);
    if ((tid & 31) == 0) red[tid >> 5] = s;
    __syncthreads();
    s = red[0];
#pragma unroll
    for (int w = 1; w < 8; w++) s += red[w];
    const float inv = 1.0f / s;

    int k = 0;
    for (int i = tid; i < n; i += 256) Lrow[i] = v[k++] * inv;
}

// ---------------- launch ----------------
extern "C" void kernel_launch(void* const* d_in, const int* in_sizes, int n_in,
                              void* d_out, int out_size) {
    const float* z    = (const float*)d_in[0];
    const int*   cid  = (const int*)  d_in[1];
    const float* W1   = (const float*)d_in[2];
    const float* b1   = (const float*)d_in[3];
    const float* W2   = (const float*)d_in[4];
    const float* b2   = (const float*)d_in[5];
    const float* Wa   = (const float*)d_in[6];
    const float* ba   = (const float*)d_in[7];
    const float* Xbuf = (const float*)d_in[8];
    float* out = (float*)d_out;

    static bool attr_done = false;
    if (!attr_done) {
        cudaFuncSetAttribute(k_mma_gemm1,  cudaFuncAttributeMaxDynamicSharedMemorySize, SMEM_BYTES);
        cudaFuncSetAttribute(k_mma_gemm2,  cudaFuncAttributeMaxDynamicSharedMemorySize, SMEM_BYTES);
        cudaFuncSetAttribute(k_mma_logits, cudaFuncAttributeMaxDynamicSharedMemorySize, SMEM_BYTES);
        cudaFuncSetAttribute(k_mma_synth,  cudaFuncAttributeMaxDynamicSharedMemorySize, SMEM_BYTES);
        attr_done = true;
    }

    k_zero<<<1, 32>>>();
    k_count<<<Bn / 256, 256>>>(cid);
    k_prefix<<<1, 1>>>();
    k_scatter<<<Bn / 256, 256>>>(cid);

    k_mma_gemm1<<<dim3(HID / 128, Bn / 128), 256, SMEM_BYTES>>>(z, cid, W1, b1);
    k_mma_gemm2<<<dim3(HID / 128, Bn / 128), 256, SMEM_BYTES>>>(W2, b2);
    k_mma_logits<<<dim3(NMAXP / 128, Bn / 128, NCLS), 256, SMEM_BYTES>>>(Wa, ba);
    k_softmax<<<Bn, 256>>>(cid);
    k_mma_synth<<<dim3(Dd / 128, Bn / 128, NCLS), 256, SMEM_BYTES>>>(Xbuf, out);
}

// round 7
// speedup vs baseline: 4.6997x; 1.0984x over previous
#include <cuda_runtime.h>
#include <cuda_bf16.h>
#include <math.h>
#include <stdint.h>

// Problem constants
#define Bn      2048
#define LATENT  128
#define NCLS    8
#define HID     1024
#define Dd      512
#define NMAXP   4096

// smem stage geometry: A and B planes both 128 rows x 80B (40 bf16, 32 used)
#define PROW       80
#define PLANE      (128 * PROW)          // 10240
#define B_OFF      (2 * PLANE)           // 20480
#define STAGE      (4 * PLANE)           // 40960
#define SMEM_BYTES (2 * STAGE)           // 81920 (double buffer -> 2 CTAs/SM)

__device__ __constant__ int d_COUNTS[NCLS] = {1024, 1536, 2048, 2560, 3072, 3584, 3840, 4096};

// ---- scratch (static device memory; only ever referenced from device code) ----
__device__ __align__(16) __nv_bfloat16 g_zhi[Bn * LATENT],  g_zlo[Bn * LATENT];
__device__ __align__(16) __nv_bfloat16 g_W1Thi[HID * LATENT], g_W1Tlo[HID * LATENT];   // [n][k]
__device__ __align__(16) __nv_bfloat16 g_W2Thi[HID * HID],    g_W2Tlo[HID * HID];      // [n][k]
__device__ __align__(16) __nv_bfloat16 g_WaThi[(size_t)NCLS * NMAXP * HID], g_WaTlo[(size_t)NCLS * NMAXP * HID];
__device__ __align__(16) __nv_bfloat16 g_XbThi[(size_t)NCLS * Dd * NMAXP],  g_XbTlo[(size_t)NCLS * Dd * NMAXP];
__device__ __align__(16) __nv_bfloat16 g_hhi[Bn * HID],  g_hlo[Bn * HID];
__device__ __align__(16) __nv_bfloat16 g_thi[Bn * HID],  g_tlo[Bn * HID];
__device__ __align__(16) __nv_bfloat16 g_ahi[(size_t)Bn * NMAXP], g_alo[(size_t)Bn * NMAXP];
__device__ float g_logits[(size_t)Bn * NMAXP];
__device__ int   g_cnt[NCLS], g_off[NCLS], g_fill[NCLS], g_rowidx[Bn];

// ---------------- helpers ----------------
__device__ __forceinline__ uint32_t smem_u32(const void* p) {
    uint32_t a;
    asm("{ .reg .u64 t; cvta.to.shared.u64 t, %1; cvt.u32.u64 %0, t; }" : "=r"(a) : "l"(p));
    return a;
}
__device__ __forceinline__ uint32_t pk2(__nv_bfloat16 a, __nv_bfloat16 b) {
    return (uint32_t)__bfloat16_as_ushort(a) | ((uint32_t)__bfloat16_as_ushort(b) << 16);
}
__device__ __forceinline__ void split2(float x, __nv_bfloat16& h, __nv_bfloat16& l) {
    h = __float2bfloat16(x);
    l = __float2bfloat16(x - __bfloat162float(h));
}
__device__ __forceinline__ float gelu_exact(float x) {
    return 0.5f * x * (1.0f + erff(x * 0.70710678118654752440f));
}

__device__ __forceinline__ void cp16(uint32_t dst, const void* src) {
    asm volatile("cp.async.cg.shared.global [%0], [%1], 16;" :: "r"(dst), "l"(src));
}
#define CP_COMMIT() asm volatile("cp.async.commit_group;" ::: "memory")
#define CP_WAIT(n)  asm volatile("cp.async.wait_group %0;" :: "n"(n) : "memory")

__device__ __forceinline__ void ldm_x4(uint32_t addr, uint32_t* r) {
    asm volatile("ldmatrix.sync.aligned.m8n8.x4.shared.b16 {%0,%1,%2,%3}, [%4];"
        : "=r"(r[0]), "=r"(r[1]), "=r"(r[2]), "=r"(r[3]) : "r"(addr));
}
__device__ __forceinline__ void ldm_x2(uint32_t addr, uint32_t* r) {
    asm volatile("ldmatrix.sync.aligned.m8n8.x2.shared.b16 {%0,%1}, [%2];"
        : "=r"(r[0]), "=r"(r[1]) : "r"(addr));
}
__device__ __forceinline__ void mma16816(float* c, const uint32_t* a, const uint32_t* b) {
    asm volatile(
        "mma.sync.aligned.m16n8k16.row.col.f32.bf16.bf16.f32 "
        "{%0,%1,%2,%3}, {%4,%5,%6,%7}, {%8,%9}, {%0,%1,%2,%3};"
        : "+f"(c[0]), "+f"(c[1]), "+f"(c[2]), "+f"(c[3])
        : "r"(a[0]), "r"(a[1]), "r"(a[2]), "r"(a[3]), "r"(b[0]), "r"(b[1]));
}

// ---------------- conversion kernels ----------------
// Destinations are device globals referenced ONLY from device code.
__global__ void __launch_bounds__(256) k_conv_z(const float* __restrict__ src) {
    size_t i = ((size_t)blockIdx.x * 256 + threadIdx.x) * 4;
    float4 v = *(const float4*)(src + i);
    __nv_bfloat16 h0, h1, h2, h3, l0, l1, l2, l3;
    split2(v.x, h0, l0); split2(v.y, h1, l1); split2(v.z, h2, l2); split2(v.w, h3, l3);
    *(uint2*)(g_zhi + i) = make_uint2(pk2(h0, h1), pk2(h2, h3));
    *(uint2*)(g_zlo + i) = make_uint2(pk2(l0, l1), pk2(l2, l3));
}

// Tiled transpose+split body: in [Rk][Cn] fp32 -> out [Cn][Rk] bf16 hi/lo planes.
__device__ __forceinline__ void transconv_body(
    const float* __restrict__ s, __nv_bfloat16* __restrict__ ho,
    __nv_bfloat16* __restrict__ lp, int Rk, int Cn, int k0, int n0)
{
    __shared__ float tile[32][33];
    const int tx = threadIdx.x & 31, ty = threadIdx.x >> 5;   // 32 x 8
#pragma unroll
    for (int j = 0; j < 4; ++j)
        tile[ty + j * 8][tx] = s[(size_t)(k0 + ty + j * 8) * Cn + n0 + tx];
    __syncthreads();
#pragma unroll
    for (int j = 0; j < 4; ++j) {
        float v = tile[tx][ty + j * 8];
        __nv_bfloat16 h, l;
        split2(v, h, l);
        size_t o = (size_t)(n0 + ty + j * 8) * Rk + k0 + tx;
        ho[o] = h;
        lp[o] = l;
    }
}

__global__ void __launch_bounds__(256) k_conv_w1(const float* __restrict__ W1) {
    transconv_body(W1, g_W1Thi, g_W1Tlo, LATENT, HID, blockIdx.y * 32, blockIdx.x * 32);
}
__global__ void __launch_bounds__(256) k_conv_w2(const float* __restrict__ W2) {
    transconv_body(W2, g_W2Thi, g_W2Tlo, HID, HID, blockIdx.y * 32, blockIdx.x * 32);
}
__global__ void __launch_bounds__(256) k_conv_wa(const float* __restrict__ Wa) {
    const int cls = blockIdx.z;
    const int n0 = blockIdx.x * 32;
    if (n0 >= d_COUNTS[cls]) return;
    transconv_body(Wa + (size_t)cls * HID * NMAXP,
                   g_WaThi + (size_t)cls * NMAXP * HID,
                   g_WaTlo + (size_t)cls * NMAXP * HID,
                   HID, NMAXP, blockIdx.y * 32, n0);
}
__global__ void __launch_bounds__(256) k_conv_xb(const float* __restrict__ Xb) {
    const int cls = blockIdx.z;
    const int k0 = blockIdx.y * 32;
    if (k0 >= d_COUNTS[cls]) return;
    transconv_body(Xb + (size_t)cls * NMAXP * Dd,
                   g_XbThi + (size_t)cls * Dd * NMAXP,
                   g_XbTlo + (size_t)cls * Dd * NMAXP,
                   NMAXP, Dd, k0, blockIdx.x * 32);
}

// ---------------- mainloop (cp.async, double buffered) ----------------
// smem stage: AHI @0, ALO @PLANE, BHI @B_OFF, BLO @B_OFF+PLANE; all 128 rows x 80B.
template<bool GATHER>
__device__ __forceinline__ void issue_stage(
    const __nv_bfloat16* __restrict__ Ahi, const __nv_bfloat16* __restrict__ Alo, int lda,
    const __nv_bfloat16* __restrict__ BThi, const __nv_bfloat16* __restrict__ BTlo, int ldk,
    int k0, int m0, int n0, const int* rowsm, int tid, uint32_t sbase)
{
#pragma unroll
    for (int it = 0; it < 4; ++it) {
        int idx = tid + it * 256;
        int p = idx >> 9, rem = idx & 511;
        int r = rem >> 2, q = rem & 3;
        const __nv_bfloat16* src = (p ? Alo : Ahi)
            + (size_t)(GATHER ? rowsm[r] : (m0 + r)) * lda + k0 + q * 8;
        cp16(sbase + p * PLANE + r * PROW + q * 16, src);
    }
#pragma unroll
    for (int it = 0; it < 4; ++it) {
        int idx = tid + it * 256;
        int p = idx >> 9, rem = idx & 511;
        int n = rem >> 2, q = rem & 3;
        const __nv_bfloat16* src = (p ? BTlo : BThi) + (size_t)(n0 + n) * ldk + k0 + q * 8;
        cp16(sbase + B_OFF + p * PLANE + n * PROW + q * 16, src);
    }
}

// Round-3-proven compute stage (B [n][k] in smem, plain ldmatrix)
__device__ __forceinline__ void compute_stage(uint32_t sbase, int lane, int wm, int wn,
                                              float acc[4][4][4])
{
#pragma unroll
    for (int ks = 0; ks < 2; ++ks) {
        uint32_t ahi[4][4], alo[4][4];
#pragma unroll
        for (int mt = 0; mt < 4; ++mt) {
            uint32_t row = (uint32_t)(wm + mt * 16 + (lane & 15));
            uint32_t addr = sbase + row * PROW + ks * 32 + ((uint32_t)(lane >> 4)) * 16;
            ldm_x4(addr, ahi[mt]);
            ldm_x4(addr + PLANE, alo[mt]);
        }
#pragma unroll
        for (int nt = 0; nt < 4; ++nt) {
            uint32_t nrow = (uint32_t)(wn + nt * 8 + (lane & 7));
            uint32_t baddr = sbase + B_OFF + nrow * PROW + ks * 32
                           + ((uint32_t)((lane >> 3) & 1)) * 16;
            uint32_t bh[2], bl[2];
            ldm_x2(baddr, bh);
            ldm_x2(baddr + PLANE, bl);
#pragma unroll
            for (int mt = 0; mt < 4; ++mt) {
                mma16816(acc[mt][nt], ahi[mt], bh);
                mma16816(acc[mt][nt], ahi[mt], bl);
                mma16816(acc[mt][nt], alo[mt], bh);
            }
        }
    }
}

template<bool GATHER>
__device__ __forceinline__ void mma_mainloop(
    const __nv_bfloat16* __restrict__ Ahi, const __nv_bfloat16* __restrict__ Alo, int lda,
    const __nv_bfloat16* __restrict__ BThi, const __nv_bfloat16* __restrict__ BTlo, int ldk,
    int K, uint32_t smb, const int* rowsm, int m0, int n0, float acc[4][4][4])
{
    const int tid = threadIdx.x;
    const int lane = tid & 31, warp = tid >> 5;
    const int wm = (warp & 1) * 64, wn = (warp >> 1) * 32;
    const int S = K >> 5;   // always >= 4 here

    issue_stage<GATHER>(Ahi, Alo, lda, BThi, BTlo, ldk, 0, m0, n0, rowsm, tid, smb);
    CP_COMMIT();

    for (int s = 0; s < S; ++s) {
        if (s + 1 < S) {
            // target buffer (s+1)&1 was consumed at iteration s-1 (or is fresh)
            issue_stage<GATHER>(Ahi, Alo, lda, BThi, BTlo, ldk, (s + 1) << 5,
                                m0, n0, rowsm, tid, smb + ((s + 1) & 1) * STAGE);
            CP_COMMIT();
            CP_WAIT(1);          // in-order completion -> stage s has landed
        } else {
            CP_WAIT(0);
        }
        __syncthreads();
        compute_stage(smb + (s & 1) * STAGE, lane, wm, wn, acc);
        __syncthreads();
    }
}

// ---------------- bucketing ----------------
__global__ void k_zero() {
    int t = threadIdx.x;
    if (t < NCLS) { g_cnt[t] = 0; g_fill[t] = 0; }
}
__global__ void k_count(const int* __restrict__ cid) {
    int b = blockIdx.x * 256 + threadIdx.x;
    if (b < Bn) atomicAdd(&g_cnt[cid[b]], 1);
}
__global__ void k_prefix() {
    int acc = 0;
    for (int c = 0; c < NCLS; c++) { g_off[c] = acc; acc += g_cnt[c]; }
}
__global__ void k_scatter(const int* __restrict__ cid) {
    int b = blockIdx.x * 256 + threadIdx.x;
    if (b < Bn) {
        int c = cid[b];
        g_rowidx[g_off[c] + atomicAdd(&g_fill[c], 1)] = b;
    }
}

// ---------------- GEMM kernels ----------------
__global__ void __launch_bounds__(256)
k_mma_gemm1(const int* __restrict__ cid, const float* __restrict__ W1,
            const float* __restrict__ b1)
{
    extern __shared__ char sm[];
    const int n0 = blockIdx.x * 128, m0 = blockIdx.y * 128;
    const uint32_t smb = smem_u32(sm);
    const int tid = threadIdx.x, lane = tid & 31, warp = tid >> 5;
    const int wm = (warp & 1) * 64, wn = (warp >> 1) * 32;

    float acc[4][4][4] = {};
    mma_mainloop<false>(g_zhi, g_zlo, LATENT, g_W1Thi, g_W1Tlo, LATENT,
                        LATENT, smb, nullptr, m0, n0, acc);

#pragma unroll
    for (int mt = 0; mt < 4; ++mt) {
        int r0 = wm + mt * 16 + (lane >> 2);
#pragma unroll
        for (int half = 0; half < 2; ++half) {
            int row = m0 + r0 + half * 8;
            int c = cid[row];
            const float* wext = W1 + (size_t)(LATENT + c) * HID;
#pragma unroll
            for (int nt = 0; nt < 4; ++nt) {
                int col = n0 + wn + nt * 8 + (lane & 3) * 2;
                float v0 = gelu_exact(acc[mt][nt][half * 2 + 0] + b1[col]     + wext[col]);
                float v1 = gelu_exact(acc[mt][nt][half * 2 + 1] + b1[col + 1] + wext[col + 1]);
                __nv_bfloat16 h0, h1, l0, l1;
                split2(v0, h0, l0); split2(v1, h1, l1);
                size_t o = (size_t)row * HID + col;
                *(uint32_t*)(g_hhi + o) = pk2(h0, h1);
                *(uint32_t*)(g_hlo + o) = pk2(l0, l1);
            }
        }
    }
}

__global__ void __launch_bounds__(256)
k_mma_gemm2(const float* __restrict__ b2)
{
    extern __shared__ char sm[];
    const int n0 = blockIdx.x * 128, m0 = blockIdx.y * 128;
    const uint32_t smb = smem_u32(sm);
    const int tid = threadIdx.x, lane = tid & 31, warp = tid >> 5;
    const int wm = (warp & 1) * 64, wn = (warp >> 1) * 32;

    float acc[4][4][4] = {};
    mma_mainloop<false>(g_hhi, g_hlo, HID, g_W2Thi, g_W2Tlo, HID,
                        HID, smb, nullptr, m0, n0, acc);

#pragma unroll
    for (int mt = 0; mt < 4; ++mt) {
        int r0 = wm + mt * 16 + (lane >> 2);
#pragma unroll
        for (int half = 0; half < 2; ++half) {
            int row = m0 + r0 + half * 8;
#pragma unroll
            for (int nt = 0; nt < 4; ++nt) {
                int col = n0 + wn + nt * 8 + (lane & 3) * 2;
                float v0 = gelu_exact(acc[mt][nt][half * 2 + 0] + b2[col]);
                float v1 = gelu_exact(acc[mt][nt][half * 2 + 1] + b2[col + 1]);
                __nv_bfloat16 h0, h1, l0, l1;
                split2(v0, h0, l0); split2(v1, h1, l1);
                size_t o = (size_t)row * HID + col;
                *(uint32_t*)(g_thi + o) = pk2(h0, h1);
                *(uint32_t*)(g_tlo + o) = pk2(l0, l1);
            }
        }
    }
}

__global__ void __launch_bounds__(256)
k_mma_logits(const float* __restrict__ ba)
{
    extern __shared__ char sm[];
    __shared__ int rows[128];
    const int c = blockIdx.z;
    const int mcnt = g_cnt[c];
    const int m0 = blockIdx.y * 128;
    if (m0 >= mcnt) return;
    const int n0 = blockIdx.x * 128;
    if (n0 >= d_COUNTS[c]) return;

    const uint32_t smb = smem_u32(sm);
    const int tid = threadIdx.x, lane = tid & 31, warp = tid >> 5;
    const int wm = (warp & 1) * 64, wn = (warp >> 1) * 32;

    if (tid < 128) {
        int mi = m0 + tid;
        rows[tid] = g_rowidx[g_off[c] + (mi < mcnt ? mi : 0)];
    }
    __syncthreads();

    float acc[4][4][4] = {};
    mma_mainloop<true>(g_thi, g_tlo, HID,
                       g_WaThi + (size_t)c * NMAXP * HID, g_WaTlo + (size_t)c * NMAXP * HID,
                       HID, HID, smb, rows, m0, n0, acc);

    const float* bap = ba + (size_t)c * NMAXP;
#pragma unroll
    for (int mt = 0; mt < 4; ++mt) {
        int r0 = wm + mt * 16 + (lane >> 2);
#pragma unroll
        for (int half = 0; half < 2; ++half) {
            int mi = r0 + half * 8;
            if (m0 + mi < mcnt) {
                int grow = rows[mi];
#pragma unroll
                for (int nt = 0; nt < 4; ++nt) {
                    int col = n0 + wn + nt * 8 + (lane & 3) * 2;
                    float v0 = acc[mt][nt][half * 2 + 0] + bap[col];
                    float v1 = acc[mt][nt][half * 2 + 1] + bap[col + 1];
                    *(float2*)(g_logits + (size_t)grow * NMAXP + col) = make_float2(v0, v1);
                }
            }
        }
    }
}

__global__ void __launch_bounds__(256)
k_mma_synth(float* __restrict__ out)
{
    extern __shared__ char sm[];
    __shared__ int rows[128];
    const int c = blockIdx.z;
    const int mcnt = g_cnt[c];
    const int m0 = blockIdx.y * 128;
    if (m0 >= mcnt) return;
    const int n0 = blockIdx.x * 128;
    const int K = d_COUNTS[c];

    const uint32_t smb = smem_u32(sm);
    const int tid = threadIdx.x, lane = tid & 31, warp = tid >> 5;
    const int wm = (warp & 1) * 64, wn = (warp >> 1) * 32;

    if (tid < 128) {
        int mi = m0 + tid;
        rows[tid] = g_rowidx[g_off[c] + (mi < mcnt ? mi : 0)];
    }
    __syncthreads();

    float acc[4][4][4] = {};
    mma_mainloop<true>(g_ahi, g_alo, NMAXP,
                       g_XbThi + (size_t)c * Dd * NMAXP, g_XbTlo + (size_t)c * Dd * NMAXP,
                       NMAXP, K, smb, rows, m0, n0, acc);

#pragma unroll
    for (int mt = 0; mt < 4; ++mt) {
        int r0 = wm + mt * 16 + (lane >> 2);
#pragma unroll
        for (int half = 0; half < 2; ++half) {
            int mi = r0 + half * 8;
            if (m0 + mi < mcnt) {
                int grow = rows[mi];
#pragma unroll
                for (int nt = 0; nt < 4; ++nt) {
                    int col = n0 + wn + nt * 8 + (lane & 3) * 2;
                    *(float2*)(out + (size_t)grow * Dd + col) =
                        make_float2(acc[mt][nt][half * 2 + 0], acc[mt][nt][half * 2 + 1]);
                }
            }
        }
    }
}

// ---------------- softmax (fp32 logits -> bf16 hi/lo alpha) ----------------
__global__ void __launch_bounds__(256) k_softmax(const int* __restrict__ cid) {
    const int b = blockIdx.x;
    const int c = cid[b];
    const int n = d_COUNTS[c];
    const float* Lrow = g_logits + (size_t)b * NMAXP;
    const int tid = threadIdx.x;

    float v[16];
    int cnt = 0;
    float mx = -INFINITY;
    for (int i = tid; i < n; i += 256) {
        float x = Lrow[i];
        v[cnt++] = x;
        mx = fmaxf(mx, x);
    }
    __shared__ float red[8];
#pragma unroll
    for (int o = 16; o; o >>= 1) mx = fmaxf(mx, __shfl_xor_sync(0xFFFFFFFFu, mx, o));
    if ((tid & 31) == 0) red[tid >> 5] = mx;
    __syncthreads();
    mx = red[0];
#pragma unroll
    for (int w = 1; w < 8; w++) mx = fmaxf(mx, red[w]);
    __syncthreads();

    float s = 0.0f;
    for (int k = 0; k < cnt; k++) {
        float e = expf(v[k] - mx);
        v[k] = e;
        s += e;
    }
#pragma unroll
    for (int o = 16; o; o >>= 1) s += __shfl_xor_sync(0xFFFFFFFFu, s, o);
    if ((tid & 31) == 0) red[tid >> 5] = s;
    __syncthreads();
    s = red[0];
#pragma unroll
    for (int w = 1; w < 8; w++) s += red[w];
    const float inv = 1.0f / s;

    __nv_bfloat16* ahi = g_ahi + (size_t)b * NMAXP;
    __nv_bfloat16* alo = g_alo + (size_t)b * NMAXP;
    int k = 0;
    for (int i = tid; i < n; i += 256) {
        float a = v[k++] * inv;
        __nv_bfloat16 h, l;
        split2(a, h, l);
        ahi[i] = h;
        alo[i] = l;
    }
}

// ---------------- launch ----------------
extern "C" void kernel_launch(void* const* d_in, const int* in_sizes, int n_in,
                              void* d_out, int out_size) {
    const float* z    = (const float*)d_in[0];
    const int*   cid  = (const int*)  d_in[1];
    const float* W1   = (const float*)d_in[2];
    const float* b1   = (const float*)d_in[3];
    const float* W2   = (const float*)d_in[4];
    const float* b2   = (const float*)d_in[5];
    const float* Wa   = (const float*)d_in[6];
    const float* ba   = (const float*)d_in[7];
    const float* Xbuf = (const float*)d_in[8];
    float* out = (float*)d_out;

    cudaFuncSetAttribute(k_mma_gemm1,  cudaFuncAttributeMaxDynamicSharedMemorySize, SMEM_BYTES);
    cudaFuncSetAttribute(k_mma_gemm2,  cudaFuncAttributeMaxDynamicSharedMemorySize, SMEM_BYTES);
    cudaFuncSetAttribute(k_mma_logits, cudaFuncAttributeMaxDynamicSharedMemorySize, SMEM_BYTES);
    cudaFuncSetAttribute(k_mma_synth,  cudaFuncAttributeMaxDynamicSharedMemorySize, SMEM_BYTES);

    k_zero<<<1, 32>>>();
    k_count<<<Bn / 256, 256>>>(cid);
    k_prefix<<<1, 1>>>();
    k_scatter<<<Bn / 256, 256>>>(cid);

    // conversions: destinations are device globals referenced inside the kernels
    k_conv_z<<<(Bn * LATENT) / 1024, 256>>>(z);
    k_conv_w1<<<dim3(HID / 32, LATENT / 32), 256>>>(W1);
    k_conv_w2<<<dim3(HID / 32, HID / 32), 256>>>(W2);
    k_conv_wa<<<dim3(NMAXP / 32, HID / 32, NCLS), 256>>>(Wa);
    k_conv_xb<<<dim3(Dd / 32, NMAXP / 32, NCLS), 256>>>(Xbuf);

    k_mma_gemm1<<<dim3(HID / 128, Bn / 128), 256, SMEM_BYTES>>>(cid, W1, b1);
    k_mma_gemm2<<<dim3(HID / 128, Bn / 128), 256, SMEM_BYTES>>>(b2);
    k_mma_logits<<<dim3(NMAXP / 128, Bn / 128, NCLS), 256, SMEM_BYTES>>>(ba);
    k_softmax<<<Bn, 256>>>(cid);
    k_mma_synth<<<dim3(Dd / 128, Bn / 128, NCLS), 256, SMEM_BYTES>>>(out);
}